// round 16
// baseline (speedup 1.0000x reference)
#include <cuda_runtime.h>
#include <cuda_fp16.h>
#include <cstdint>

// out = x @ W^T + bias  (memristor constants cancel algebraically; see R1).
// Legacy HMMA (mma.sync.m16n8k16) — harness targets compute_103, no tcgen05.
//
// R16: barrier-free register GEMM. R14->R15 showed elapsed is invariant to
// warp distribution at fixed chip warps; tensor pipe is ~70% idle because the
// per-iter group barrier convoys warps into LDSM-burst/MMA-burst phases.
// Fix: prepass converts X,W to fp16 globals; the GEMM loads mma fragments
// DIRECTLY from global per warp (fragment lane layout == the R6-validated
// ldmatrix mapping; each LDG.32 is 8 rows x 16B, sector-coalesced, L2-hot),
// double-buffered one k16-step ahead. Mainloop: no SMEM, no bar.sync, no
// LDSM/STS -- warps decorrelate, tensor pipe stays fed.
// Warp tile 32x64, split-K x4 per 128-thread CTA; grid 16x32=512 CTAs (~4/SM,
// single wave). SMEM only in the epilogue reduction. rel_err 2.9346e-4.

namespace {
constexpr int M = 512, N = 2048, K = 2048;
constexpr int TM = 32, TN = 64;            // warp output tile
constexpr int SPLITS = 4;
constexpr int KS = K / SPLITS;             // 512 per split
constexpr int NSTEP = KS / 16;             // 32 k16 steps
constexpr int XT = (M * K) / 8;            // prepass threads covering X
}  // namespace

__device__ __align__(16) __half g_Xh[M * K];   // 2 MB
__device__ __align__(16) __half g_Wh[N * K];   // 8 MB

__device__ __forceinline__ void mma16816(float d[4], const unsigned a[4],
                                         const unsigned b[2]) {
    asm volatile(
        "mma.sync.aligned.m16n8k16.row.col.f32.f16.f16.f32 "
        "{%0,%1,%2,%3}, {%4,%5,%6,%7}, {%8,%9}, {%0,%1,%2,%3};"
        : "+f"(d[0]), "+f"(d[1]), "+f"(d[2]), "+f"(d[3])
        : "r"(a[0]), "r"(a[1]), "r"(a[2]), "r"(a[3]), "r"(b[0]), "r"(b[1]));
}

__device__ __forceinline__ uint2 pack_f16x4(float4 v) {
    unsigned h0, h1;
    asm("cvt.rn.f16x2.f32 %0, %1, %2;" : "=r"(h0) : "f"(v.y), "f"(v.x));
    asm("cvt.rn.f16x2.f32 %0, %1, %2;" : "=r"(h1) : "f"(v.w), "f"(v.z));
    return make_uint2(h0, h1);
}

// ---------------- Prepass: fp32 -> fp16 for X and W ----------------
__global__ __launch_bounds__(256)
void convert_kernel(const float* __restrict__ X, const float* __restrict__ W)
{
    const int gid = blockIdx.x * 256 + threadIdx.x;   // 8 elems per thread
    const float4* src;
    __half* dst;
    int off;                                          // in float4 units
    if (gid < XT) { src = reinterpret_cast<const float4*>(X); dst = g_Xh; off = gid * 2; }
    else          { src = reinterpret_cast<const float4*>(W); dst = g_Wh; off = (gid - XT) * 2; }
    const float4 v0 = src[off], v1 = src[off + 1];
    const uint2 h0 = pack_f16x4(v0), h1 = pack_f16x4(v1);
    *reinterpret_cast<uint4*>(dst + off * 4) = make_uint4(h0.x, h0.y, h1.x, h1.y);
}

// ---------------- Barrier-free register GEMM ----------------
__global__ __launch_bounds__(128, 4)
void memristor_reg_kernel(const float* __restrict__ bias, float* __restrict__ O)
{
    __shared__ float red[SPLITS][TM][TN + 2];     // padded: bank-spread rows

    const int tid  = threadIdx.x;
    const int lane = tid & 31;
    const int s    = tid >> 5;                    // k-split 0..3
    const int R0   = blockIdx.x * TM;
    const int N0   = blockIdx.y * TN;
    const int r    = lane >> 2;                   // fragment row within 8
    const int c2   = (lane & 3) * 2;              // fragment k-pair

    // Fragment base pointers (R6-validated m16n8k16 lane layout):
    //   A: a0={m+r,  k+c2}, a1={m+r+8, k+c2}, a2/a3 = +8 in k
    //   B: b0={n+r,  k+c2}, b1 = +8 in k      (W rows are the n dimension)
    const __half* Ap = g_Xh + (size_t)(R0 + r) * K + s * KS + c2;
    const __half* Bp = g_Wh + (size_t)(N0 + r) * K + s * KS + c2;

    float acc[2][8][4] = {};                      // 64 regs
    unsigned a[2][2][4], b[2][8][2];              // [buf][ma/na][reg]

    auto LDF = [&](int st, int buf) {
        const int ko = st * 16;
        #pragma unroll
        for (int ma = 0; ma < 2; ++ma) {
            a[buf][ma][0] = *(const unsigned*)(Ap + (size_t)(ma * 16    ) * K + ko);
            a[buf][ma][1] = *(const unsigned*)(Ap + (size_t)(ma * 16 + 8) * K + ko);
            a[buf][ma][2] = *(const unsigned*)(Ap + (size_t)(ma * 16    ) * K + ko + 8);
            a[buf][ma][3] = *(const unsigned*)(Ap + (size_t)(ma * 16 + 8) * K + ko + 8);
        }
        #pragma unroll
        for (int na = 0; na < 8; ++na) {
            b[buf][na][0] = *(const unsigned*)(Bp + (size_t)(na * 8) * K + ko);
            b[buf][na][1] = *(const unsigned*)(Bp + (size_t)(na * 8) * K + ko + 8);
        }
    };
    auto MMAS = [&](int buf) {
        #pragma unroll
        for (int ma = 0; ma < 2; ++ma)
            #pragma unroll
            for (int na = 0; na < 8; ++na)
                mma16816(acc[ma][na], a[buf][ma], b[buf][na]);
    };

    // Mainloop: one-step-ahead register double buffer; no barriers, no SMEM.
    LDF(0, 0);
    #pragma unroll 1
    for (int st = 0; st < NSTEP; st += 2) {
        LDF(st + 1, 1);                           // st+1 <= 31 always (NSTEP even)
        MMAS(0);
        if (st + 2 < NSTEP) LDF(st + 2, 0);
        MMAS(1);
    }

    // ---- epilogue: spill all 4 split-partials, reduce CTA-wide ----
    #pragma unroll
    for (int ma = 0; ma < 2; ++ma)
        #pragma unroll
        for (int na = 0; na < 8; ++na) {
            *(float2*)&red[s][ma * 16 + r    ][na * 8 + c2] =
                make_float2(acc[ma][na][0], acc[ma][na][1]);
            *(float2*)&red[s][ma * 16 + r + 8][na * 8 + c2] =
                make_float2(acc[ma][na][2], acc[ma][na][3]);
        }
    __syncthreads();

    #pragma unroll
    for (int j = 0; j < 8; ++j) {
        const int p   = tid * 8 + j;              // float2-pair index 0..1023
        const int row = p >> 5;                   // 0..31
        const int col = (p & 31) * 2;             // 0..62
        float2 v  = *(const float2*)&red[0][row][col];
        float2 v1 = *(const float2*)&red[1][row][col];
        float2 v2 = *(const float2*)&red[2][row][col];
        float2 v3 = *(const float2*)&red[3][row][col];
        const float2 bb = *(const float2*)(bias + N0 + col);
        v.x += v1.x + v2.x + v3.x + bb.x;
        v.y += v1.y + v2.y + v3.y + bb.y;
        *(float2*)(O + (size_t)(R0 + row) * N + N0 + col) = v;
    }
}

extern "C" void kernel_launch(void* const* d_in, const int* in_sizes, int n_in,
                              void* d_out, int out_size)
{
    (void)in_sizes; (void)n_in; (void)out_size;
    const float* x    = (const float*)d_in[0];
    const float* w    = (const float*)d_in[1];
    const float* bias = (const float*)d_in[2];
    float* out        = (float*)d_out;

    const int conv_threads = (M * K + N * K) / 8;     // 655360
    convert_kernel<<<conv_threads / 256, 256>>>(x, w);

    dim3 grid(M / TM, N / TN);   // 16 x 32 = 512 CTAs of 128 threads, ~4/SM
    memristor_reg_kernel<<<grid, 128>>>(bias, out);
}

// round 17
// speedup vs baseline: 2.3428x; 2.3428x over previous
#include <cuda_runtime.h>
#include <cuda_fp16.h>
#include <cstdint>

// out = x @ W^T + bias  (memristor constants cancel algebraically; see R1).
// Legacy HMMA (mma.sync.m16n8k16) — harness targets compute_103, no tcgen05.
//
// Two-phase (R14): prepass fp32->fp16 into __device__ globals; GEMM cp.asyncs
// fp16 tiles straight to SMEM. fp16 single term, split-K x2 (2 groups x 8
// warps), 3-stage ring, one named barrier per iter.
//
// R17: break the per-k-step LDSM->MMA serial chain. COMPUTE now register-
// double-buffers fragments (loads step j+1 while issuing MMAs of step j) and
// each warp processes k-steps in a rotated order (phase = wl&3), so warps
// leave the barrier hitting different SMEM addresses instead of bursting the
// same banks. Tensor pipe was 72% idle with LDSM/MMA phase-locking as the
// last unaddressed mechanism. rel_err unchanged 2.9346e-4 (order-independent
// fp32 accumulation of identical products).

namespace {
constexpr int M = 512, N = 2048, K = 2048;
constexpr int BM = 64, BN = 128, BK = 64;
constexpr int NT_G = (K / 2) / BK;         // 16 k-tiles per group
constexpr int ROWB = 144;                  // 128B data + 16B pad: LDSM conflict-free
constexpr int A_SZ  = BM * ROWB;           // 9216
constexpr int B_SZ  = BN * ROWB;           // 18432
constexpr int OFF_B = A_SZ;
constexpr int STAGE = A_SZ + B_SZ;         // 27648
constexpr int NSTG  = 3;
constexpr int SMEM_TOTAL = 2 * NSTG * STAGE;  // 165888
constexpr int XT = (M * K) / 8;            // prepass threads covering X
}  // namespace

__device__ __align__(16) __half g_Xh[M * K];   // 2 MB
__device__ __align__(16) __half g_Wh[N * K];   // 8 MB

__device__ __forceinline__ unsigned smem_u32(const void* p) {
    unsigned a;
    asm("{ .reg .u64 t; cvta.to.shared.u64 t, %1; cvt.u32.u64 %0, t; }"
        : "=r"(a) : "l"(p));
    return a;
}

__device__ __forceinline__ void ldsm4(unsigned r[4], unsigned addr) {
    asm volatile("ldmatrix.sync.aligned.m8n8.x4.shared.b16 {%0,%1,%2,%3}, [%4];"
                 : "=r"(r[0]), "=r"(r[1]), "=r"(r[2]), "=r"(r[3]) : "r"(addr));
}

__device__ __forceinline__ void mma16816(float d[4], const unsigned a[4],
                                         const unsigned b[2]) {
    asm volatile(
        "mma.sync.aligned.m16n8k16.row.col.f32.f16.f16.f32 "
        "{%0,%1,%2,%3}, {%4,%5,%6,%7}, {%8,%9}, {%0,%1,%2,%3};"
        : "+f"(d[0]), "+f"(d[1]), "+f"(d[2]), "+f"(d[3])
        : "r"(a[0]), "r"(a[1]), "r"(a[2]), "r"(a[3]), "r"(b[0]), "r"(b[1]));
}

__device__ __forceinline__ uint2 pack_f16x4(float4 v) {
    unsigned h0, h1;
    asm("cvt.rn.f16x2.f32 %0, %1, %2;" : "=r"(h0) : "f"(v.y), "f"(v.x));
    asm("cvt.rn.f16x2.f32 %0, %1, %2;" : "=r"(h1) : "f"(v.w), "f"(v.z));
    return make_uint2(h0, h1);
}

__device__ __forceinline__ void cp_async16(unsigned dst, const void* src) {
    asm volatile("cp.async.cg.shared.global [%0], [%1], 16;"
                 :: "r"(dst), "l"(src) : "memory");
}

// ---------------- Prepass: fp32 -> fp16 for X and W ----------------
__global__ __launch_bounds__(256)
void convert_kernel(const float* __restrict__ X, const float* __restrict__ W)
{
    const int gid = blockIdx.x * 256 + threadIdx.x;   // 8 elems per thread
    const float4* src;
    __half* dst;
    int off;                                          // in float4 units
    if (gid < XT) { src = reinterpret_cast<const float4*>(X); dst = g_Xh; off = gid * 2; }
    else          { src = reinterpret_cast<const float4*>(W); dst = g_Wh; off = (gid - XT) * 2; }
    const float4 v0 = src[off], v1 = src[off + 1];
    const uint2 h0 = pack_f16x4(v0), h1 = pack_f16x4(v1);
    *reinterpret_cast<uint4*>(dst + off * 4) = make_uint4(h0.x, h0.y, h1.x, h1.y);
}

// ---------------- Mainloop GEMM ----------------
__global__ __launch_bounds__(512, 1)
void memristor_hmma_kernel(const float* __restrict__ bias, float* __restrict__ O)
{
    extern __shared__ char smem[];
    const unsigned sb = smem_u32(smem);
    const int t = threadIdx.x;
    const int lane = t & 31, wid = t >> 5;
    const int kg = wid >> 3;                      // k-group 0/1
    const int wl = wid & 7;
    const int wm = wl & 1, wn = wl >> 1;          // warp grid 2(M) x 4(N)
    const int phase = wl & 3;                     // per-warp k-step rotation
    const int m0 = blockIdx.y * BM, n0 = blockIdx.x * BN;
    const unsigned gsb = sb + (unsigned)(kg * NSTG * STAGE);

    // ---- cp.async mapping: 16B chunks; chunk c -> row c>>3, col16 c&7 ----
    const int tl = t & 255;
    const int kbase = kg * (K / 2);
    const __half* aS = g_Xh + (size_t)m0 * K + kbase;
    const __half* bS = g_Wh + (size_t)n0 * K + kbase;

    auto CPA = [&](int it, int buf) {
        const unsigned base = gsb + (unsigned)(buf * STAGE);
        const int k0 = it * BK;
        #pragma unroll
        for (int j = 0; j < 2; ++j) {             // A: 512 chunks / 256 thr
            const int c = tl + 256 * j, r = c >> 3, col = c & 7;
            cp_async16(base + (unsigned)(r * ROWB + col * 16),
                       aS + (size_t)r * K + k0 + col * 8);
        }
        #pragma unroll
        for (int j = 0; j < 4; ++j) {             // B: 1024 chunks / 256 thr
            const int c = tl + 256 * j, r = c >> 3, col = c & 7;
            cp_async16(base + OFF_B + (unsigned)(r * ROWB + col * 16),
                       bS + (size_t)r * K + k0 + col * 8);
        }
        asm volatile("cp.async.commit_group;" ::: "memory");
    };

    // ---- ldmatrix per-lane base offsets ----
    const int mi = lane >> 3, rowin = lane & 7;
    const unsigned a_lane =
        (unsigned)((wm * 32 + (mi & 1) * 8 + rowin) * ROWB + (mi >> 1) * 16);
    const unsigned b_lane =
        (unsigned)((wn * 32 + (mi >> 1) * 8 + rowin) * ROWB + (mi & 1) * 16);

    float acc[2][4][4];
    #pragma unroll
    for (int i = 0; i < 2; ++i)
        #pragma unroll
        for (int j = 0; j < 4; ++j)
            #pragma unroll
            for (int q = 0; q < 4; ++q) acc[i][j][q] = 0.0f;

    // Fragment loader for one k16 step (ks in 0..3 within the BK=64 tile).
    auto LDFR = [&](unsigned base, int ks, unsigned aF[2][4], unsigned bF[2][4]) {
        #pragma unroll
        for (int ma = 0; ma < 2; ++ma)
            ldsm4(aF[ma], base + a_lane + ma * (16 * ROWB) + ks * 32);
        #pragma unroll
        for (int g = 0; g < 2; ++g)
            ldsm4(bF[g], base + OFF_B + b_lane + g * (16 * ROWB) + ks * 32);
    };

    // R17 COMPUTE: register double-buffered fragments; k-steps processed in
    // per-warp rotated order (phase). MMAs of step j overlap LDSM of j+1.
    auto COMPUTE = [&](int buf) {
        const unsigned base = gsb + (unsigned)(buf * STAGE);
        unsigned aF[2][2][4], bF[2][2][4];        // [pipe][ma|g][4]
        LDFR(base, phase, aF[0], bF[0]);
        #pragma unroll
        for (int j = 0; j < 4; ++j) {
            if (j < 3)
                LDFR(base, (j + 1 + phase) & 3, aF[(j + 1) & 1], bF[(j + 1) & 1]);
            const int p = j & 1;
            #pragma unroll
            for (int ma = 0; ma < 2; ++ma)
                #pragma unroll
                for (int na = 0; na < 4; ++na)
                    mma16816(acc[ma][na], aF[p][ma], &bF[p][na >> 1][(na & 1) * 2]);
        }
    };

    auto GBAR = [&]() {
        asm volatile("bar.sync %0, %1;" :: "r"(kg + 1), "r"(256) : "memory");
    };

    // ---- mainloop: 3-stage ring, cp.async pipeline, one barrier/iter ----
    CPA(0, 0);
    CPA(1, 1);
    #pragma unroll 1
    for (int i = 0; i < NT_G; ++i) {
        const int buf = i % NSTG;
        if (i == NT_G - 1)
            asm volatile("cp.async.wait_group 0;" ::: "memory");
        else
            asm volatile("cp.async.wait_group 1;" ::: "memory");
        GBAR();                                   // stage-i copies visible group-wide
        if (i + 2 < NT_G) CPA(i + 2, (i + 2) % NSTG);  // overwrite safe (R10 proof)
        COMPUTE(buf);
    }

    // ---- cross-group reduction: group1 -> SMEM fp32 tile, group0 reduces ----
    float* red = reinterpret_cast<float*>(smem);  // 64x128 f32 = 32KB, aliases stages
    const int frow0 = wm * 32 + (lane >> 2);
    const int fcol0 = wn * 32 + (lane & 3) * 2;

    __syncthreads();
    if (kg == 1) {
        #pragma unroll
        for (int ma = 0; ma < 2; ++ma)
            #pragma unroll
            for (int na = 0; na < 4; ++na) {
                const int r = frow0 + ma * 16, c = fcol0 + na * 8;
                *reinterpret_cast<float2*>(&red[r * BN + c]) =
                    make_float2(acc[ma][na][0], acc[ma][na][1]);
                *reinterpret_cast<float2*>(&red[(r + 8) * BN + c]) =
                    make_float2(acc[ma][na][2], acc[ma][na][3]);
            }
    }
    __syncthreads();
    if (kg == 0) {
        #pragma unroll
        for (int ma = 0; ma < 2; ++ma)
            #pragma unroll
            for (int na = 0; na < 4; ++na) {
                const int r = frow0 + ma * 16, c = fcol0 + na * 8;
                const int row = m0 + r, col = n0 + c;
                const float2 bb = *reinterpret_cast<const float2*>(bias + col);
                const float2 p0 = *reinterpret_cast<const float2*>(&red[r * BN + c]);
                const float2 p1 = *reinterpret_cast<const float2*>(&red[(r + 8) * BN + c]);
                float2 v0 = make_float2(acc[ma][na][0] + p0.x + bb.x,
                                        acc[ma][na][1] + p0.y + bb.y);
                float2 v1 = make_float2(acc[ma][na][2] + p1.x + bb.x,
                                        acc[ma][na][3] + p1.y + bb.y);
                *reinterpret_cast<float2*>(O + (size_t)row * N + col)       = v0;
                *reinterpret_cast<float2*>(O + (size_t)(row + 8) * N + col) = v1;
            }
    }
}

extern "C" void kernel_launch(void* const* d_in, const int* in_sizes, int n_in,
                              void* d_out, int out_size)
{
    (void)in_sizes; (void)n_in; (void)out_size;
    const float* x    = (const float*)d_in[0];
    const float* w    = (const float*)d_in[1];
    const float* bias = (const float*)d_in[2];
    float* out        = (float*)d_out;

    static bool attr_set = false;
    if (!attr_set) {
        cudaFuncSetAttribute(memristor_hmma_kernel,
                             cudaFuncAttributeMaxDynamicSharedMemorySize, SMEM_TOTAL);
        attr_set = true;
    }

    const int conv_threads = (M * K + N * K) / 8;     // 655360
    convert_kernel<<<conv_threads / 256, 256>>>(x, w);

    dim3 grid(N / BN, M / BM);   // 16 x 8 = 128 CTAs
    memristor_hmma_kernel<<<grid, 512, SMEM_TOTAL>>>(bias, out);
}